// round 15
// baseline (speedup 1.0000x reference)
#include <cuda_runtime.h>
#include <cstdint>
#include <math.h>

#define NMAX   100000
#define EMAX   3400000
#define NFEAT  256
#define NHID   64
#define NHEADS 3
#define F1     192      // NHEADS*NHID
#define NCLASS 40

// ---------------- scratch (device globals; no allocations allowed) ----------
__device__ __align__(16) float g_h   [NMAX * F1];
__device__ __align__(16) float g_out1[NMAX * F1];
__device__ __align__(16) float g_h2  [NMAX * NCLASS];
__device__ float g_fd  [NMAX * NHEADS];
__device__ float g_fs  [NMAX * NHEADS];
__device__ float g_f2d [NMAX];
__device__ float g_f2s [NMAX];

__device__ int   g_is64;
__device__ int   g_cnt    [NMAX];
__device__ int   g_rowptr [NMAX + 1];
__device__ int   g_cursor [NMAX];
__device__ int   g_part   [128];
__device__ int   g_total;
__device__ int   g_csr_src[EMAX];
__device__ __align__(16) float g_csr_w [EMAX * 3];

__device__ __forceinline__ float elu1(float x) { return x > 0.f ? x : expm1f(x); }
__device__ __forceinline__ float att_w(float l) {
    float lr = l > 0.f ? l : 0.2f * l;
    return expf(-lr);
}

__device__ __forceinline__ int edge_at(const void* ei, long idx, int is64) {
    if (is64) return (int)((const long long*)ei)[idx];
    return ((const int*)ei)[idx];
}

__device__ __forceinline__ float tf32r(float x) {
    float r;
    asm("cvt.rna.tf32.f32 %0, %1;" : "=f"(r) : "f"(x));
    return r;
}

// ---------------- dtype detection -------------------------------------------
__global__ void detect_kernel(const int* __restrict__ ei32) {
    g_is64 = (ei32[1] == 0 && ei32[3] == 0 && ei32[5] == 0) ? 1 : 0;
}

// ---------------- CSR build --------------------------------------------------
__global__ void zero_cnt_kernel(int n) {
    int i = blockIdx.x * blockDim.x + threadIdx.x;
    if (i < n) g_cnt[i] = 0;
}

__global__ void count_kernel(const void* __restrict__ ei, int E) {
    int e = blockIdx.x * blockDim.x + threadIdx.x;
    if (e >= E) return;
    int is64 = g_is64;
    atomicAdd(&g_cnt[edge_at(ei, e, is64)], 1);
}

__global__ __launch_bounds__(1024) void scanA_kernel(int n) {
    __shared__ int sh[1024];
    int t = threadIdx.x;
    int i = blockIdx.x * 1024 + t;
    int v = (i < n) ? g_cnt[i] : 0;
    sh[t] = v;
    __syncthreads();
#pragma unroll
    for (int off = 1; off < 1024; off <<= 1) {
        int x = sh[t];
        int y = (t >= off) ? sh[t - off] : 0;
        __syncthreads();
        sh[t] = x + y;
        __syncthreads();
    }
    if (i < n) g_rowptr[i] = sh[t] - v;
    if (t == 1023) g_part[blockIdx.x] = sh[1023];
}

__global__ __launch_bounds__(128) void scanB_kernel(int nb) {
    __shared__ int sh[128];
    int t = threadIdx.x;
    int v = (t < nb) ? g_part[t] : 0;
    sh[t] = v;
    __syncthreads();
#pragma unroll
    for (int off = 1; off < 128; off <<= 1) {
        int x = sh[t];
        int y = (t >= off) ? sh[t - off] : 0;
        __syncthreads();
        sh[t] = x + y;
        __syncthreads();
    }
    g_part[t] = sh[t] - v;
    if (t == 127) g_total = sh[127];
}

__global__ __launch_bounds__(1024) void scanC_kernel(int n) {
    int i = blockIdx.x * 1024 + threadIdx.x;
    if (i < n) {
        int r = g_rowptr[i] + g_part[blockIdx.x];
        g_rowptr[i] = r;
        g_cursor[i] = r;
    }
    if (i == 0) g_rowptr[n] = g_total;
}

// scatter + layer1 edge weights
__global__ void scatter_kernel(const void* __restrict__ ei, int E) {
    int e = blockIdx.x * blockDim.x + threadIdx.x;
    if (e >= E) return;
    int is64 = g_is64;
    int dst = edge_at(ei, e, is64);
    int src = edge_at(ei, (long)E + e, is64);
    int pos = atomicAdd(&g_cursor[dst], 1);
    g_csr_src[pos] = src;
#pragma unroll
    for (int h = 0; h < 3; h++)
        g_csr_w[pos * 3 + h] = att_w(g_fd[dst * 3 + h] + g_fs[src * 3 + h]);
}

// ---------------- GEMM1 (tf32 TC, 3 heads, reg-staged, fused fdot1) --------
#define AS_S2 20    // A smem row stride (16 + 4 pad)
#define BS_S 200    // B smem row stride (192 + 8 pad)
#define NKT 16      // 256 / 16
__global__ __launch_bounds__(256) void gemm1_tc_kernel(
    const float* __restrict__ x, const float* __restrict__ W,
    const float* __restrict__ a1, const float* __restrict__ a2, int n)
{
    __shared__ float As[2][128 * AS_S2];   // 2 x 10240 B
    __shared__ float Bs[2][16 * BS_S];     // 2 x 12800 B

    const int m0   = blockIdx.x * 128;
    const int tid  = threadIdx.x;

    const int wid   = tid >> 5;
    const int lane  = tid & 31;
    const int warpM = wid & 1;
    const int warpN = wid >> 1;
    const int g     = lane >> 2;
    const int tg    = lane & 3;

    const int arow0 = tid >> 2;
    const int ac40  = (tid & 3) * 4;
    const int arow1 = (tid + 256) >> 2;
    const int ac41  = ((tid + 256) & 3) * 4;
    int brow[3], bcc[3];
    const float* bsrc[3];
#pragma unroll
    for (int it = 0; it < 3; it++) {
        int j    = tid + it * 256;
        brow[it] = j / 48;
        int cc   = (j % 48) * 4;
        bcc[it]  = cc;
        int head = cc >> 6;
        int hc   = cc & 63;
        bsrc[it] = W + head * NFEAT * NHID + brow[it] * NHID + hc;
    }

    float c[4][6][4];
#pragma unroll
    for (int mt = 0; mt < 4; mt++)
#pragma unroll
        for (int nt = 0; nt < 6; nt++)
#pragma unroll
            for (int r = 0; r < 4; r++) c[mt][nt][r] = 0.f;

    float4 ra0, ra1, rb[3];
    {
        int gm0 = m0 + arow0, gm1 = m0 + arow1;
        ra0 = (gm0 < n) ? *(const float4*)(x + (long)gm0 * NFEAT + ac40)
                        : make_float4(0.f, 0.f, 0.f, 0.f);
        ra1 = (gm1 < n) ? *(const float4*)(x + (long)gm1 * NFEAT + ac41)
                        : make_float4(0.f, 0.f, 0.f, 0.f);
#pragma unroll
        for (int it = 0; it < 3; it++) rb[it] = *(const float4*)(bsrc[it]);
    }
    {
        float4 v;
        v = ra0; v.x = tf32r(v.x); v.y = tf32r(v.y); v.z = tf32r(v.z); v.w = tf32r(v.w);
        *(float4*)&As[0][arow0 * AS_S2 + ac40] = v;
        v = ra1; v.x = tf32r(v.x); v.y = tf32r(v.y); v.z = tf32r(v.z); v.w = tf32r(v.w);
        *(float4*)&As[0][arow1 * AS_S2 + ac41] = v;
#pragma unroll
        for (int it = 0; it < 3; it++) {
            v = rb[it]; v.x = tf32r(v.x); v.y = tf32r(v.y); v.z = tf32r(v.z); v.w = tf32r(v.w);
            *(float4*)&Bs[0][brow[it] * BS_S + bcc[it]] = v;
        }
    }
    __syncthreads();

    for (int t = 0; t < NKT; t++) {
        const int st = t & 1;
        if (t + 1 < NKT) {
            int kt = (t + 1) * 16;
            int gm0 = m0 + arow0, gm1 = m0 + arow1;
            ra0 = (gm0 < n) ? *(const float4*)(x + (long)gm0 * NFEAT + kt + ac40)
                            : make_float4(0.f, 0.f, 0.f, 0.f);
            ra1 = (gm1 < n) ? *(const float4*)(x + (long)gm1 * NFEAT + kt + ac41)
                            : make_float4(0.f, 0.f, 0.f, 0.f);
#pragma unroll
            for (int it = 0; it < 3; it++) rb[it] = *(const float4*)(bsrc[it] + kt * NHID);
        }

        const float* Asb = As[st];
        const float* Bsb = Bs[st];
#pragma unroll
        for (int ks = 0; ks < 2; ks++) {
            const int k0 = ks * 8;
            uint32_t a[4][4];
#pragma unroll
            for (int mt = 0; mt < 4; mt++) {
                int rbase = warpM * 64 + mt * 16;
                a[mt][0] = __float_as_uint(Asb[(rbase + g)     * AS_S2 + k0 + tg]);
                a[mt][1] = __float_as_uint(Asb[(rbase + g + 8) * AS_S2 + k0 + tg]);
                a[mt][2] = __float_as_uint(Asb[(rbase + g)     * AS_S2 + k0 + tg + 4]);
                a[mt][3] = __float_as_uint(Asb[(rbase + g + 8) * AS_S2 + k0 + tg + 4]);
            }
#pragma unroll
            for (int nt = 0; nt < 6; nt++) {
                int cbase = warpN * 48 + nt * 8;
                uint32_t b0 = __float_as_uint(Bsb[(k0 + tg)     * BS_S + cbase + g]);
                uint32_t b1 = __float_as_uint(Bsb[(k0 + tg + 4) * BS_S + cbase + g]);
#pragma unroll
                for (int mt = 0; mt < 4; mt++) {
                    asm volatile(
                        "mma.sync.aligned.m16n8k8.row.col.f32.tf32.tf32.f32 "
                        "{%0,%1,%2,%3}, {%4,%5,%6,%7}, {%8,%9}, {%0,%1,%2,%3};"
                        : "+f"(c[mt][nt][0]), "+f"(c[mt][nt][1]),
                          "+f"(c[mt][nt][2]), "+f"(c[mt][nt][3])
                        : "r"(a[mt][0]), "r"(a[mt][1]), "r"(a[mt][2]), "r"(a[mt][3]),
                          "r"(b0), "r"(b1));
                }
            }
        }

        if (t + 1 < NKT) {
            const int ns = (t + 1) & 1;
            float4 v;
            v = ra0; v.x = tf32r(v.x); v.y = tf32r(v.y); v.z = tf32r(v.z); v.w = tf32r(v.w);
            *(float4*)&As[ns][arow0 * AS_S2 + ac40] = v;
            v = ra1; v.x = tf32r(v.x); v.y = tf32r(v.y); v.z = tf32r(v.z); v.w = tf32r(v.w);
            *(float4*)&As[ns][arow1 * AS_S2 + ac41] = v;
#pragma unroll
            for (int it = 0; it < 3; it++) {
                v = rb[it]; v.x = tf32r(v.x); v.y = tf32r(v.y); v.z = tf32r(v.z); v.w = tf32r(v.w);
                *(float4*)&Bs[ns][brow[it] * BS_S + bcc[it]] = v;
            }
            __syncthreads();
        }
    }

    // epilogue: write g_h
#pragma unroll
    for (int mt = 0; mt < 4; mt++) {
        int row0 = m0 + warpM * 64 + mt * 16 + g;
#pragma unroll
        for (int nt = 0; nt < 6; nt++) {
            int col = warpN * 48 + nt * 8 + tg * 2;
            if (row0 < n)
                *(float2*)(g_h + (long)row0 * F1 + col) = make_float2(c[mt][nt][0], c[mt][nt][1]);
            if (row0 + 8 < n)
                *(float2*)(g_h + (long)(row0 + 8) * F1 + col) = make_float2(c[mt][nt][2], c[mt][nt][3]);
        }
    }

    // fused fdot1: per-row d = h.a1, s = h.a2 (reduce in smem, reuse As)
    __syncthreads();                       // everyone done with As/Bs
    float* red = &As[0][0];                // 128 rows x 6 (d0,d1,d2,s0,s1,s2)
    for (int i = tid; i < 128 * 6; i += 256) red[i] = 0.f;
    __syncthreads();

    const int h0 = (warpN * 48) >> 6;
    const int h1 = (warpN * 48 + 47) >> 6;
#pragma unroll
    for (int mt = 0; mt < 4; mt++) {
#pragma unroll
        for (int half = 0; half < 2; half++) {
            int lrow = warpM * 64 + mt * 16 + g + half * 8;
            float dv[3] = {0.f, 0.f, 0.f};
            float sv[3] = {0.f, 0.f, 0.f};
#pragma unroll
            for (int nt = 0; nt < 6; nt++) {
                int col = warpN * 48 + nt * 8 + tg * 2;
                int h   = col >> 6;
                float c0 = c[mt][nt][half * 2 + 0];
                float c1 = c[mt][nt][half * 2 + 1];
                dv[h] += c0 * __ldg(a1 + col) + c1 * __ldg(a1 + col + 1);
                sv[h] += c0 * __ldg(a2 + col) + c1 * __ldg(a2 + col + 1);
            }
            for (int h = h0; h <= h1; h++) {
                atomicAdd(&red[lrow * 6 + h],     dv[h]);
                atomicAdd(&red[lrow * 6 + 3 + h], sv[h]);
            }
        }
    }
    __syncthreads();
    if (tid < 128) {
        int row = m0 + tid;
        if (row < n) {
#pragma unroll
            for (int h = 0; h < 3; h++) {
                g_fd[row * 3 + h] = red[tid * 6 + h];
                g_fs[row * 3 + h] = red[tid * 6 + 3 + h];
            }
        }
    }
}

// ---------------- layer1 aggregation (fp32 gather, 8-edge unroll) ----------
__global__ __launch_bounds__(64) void agg1_kernel(int n) {
    int node = blockIdx.x;
    if (node >= n) return;
    int t = threadIdx.x;
    int rs = g_rowptr[node];
    int re = g_rowptr[node + 1];
    bool active = t < 48;
    int head = t >> 4;

    float ax = 0.f, ay = 0.f, az = 0.f, aw = 0.f, den = 0.f;
    int j = rs;
    for (; j + 7 < re; j += 8) {
        int s[8];
#pragma unroll
        for (int u = 0; u < 8; u++) s[u] = g_csr_src[j + u];
        if (active) {
            float w[8];
#pragma unroll
            for (int u = 0; u < 8; u++) w[u] = g_csr_w[(j + u) * 3 + head];
            float4 v[8];
#pragma unroll
            for (int u = 0; u < 8; u++)
                v[u] = *(const float4*)(g_h + (long)s[u] * F1 + t * 4);
#pragma unroll
            for (int u = 0; u < 8; u++) {
                ax += w[u] * v[u].x;
                ay += w[u] * v[u].y;
                az += w[u] * v[u].z;
                aw += w[u] * v[u].w;
                den += w[u];
            }
        }
    }
    for (; j + 1 < re; j += 2) {
        int s0 = g_csr_src[j];
        int s1 = g_csr_src[j + 1];
        if (active) {
            float w0 = g_csr_w[(j + 0) * 3 + head];
            float w1 = g_csr_w[(j + 1) * 3 + head];
            float4 v0 = *(const float4*)(g_h + (long)s0 * F1 + t * 4);
            float4 v1 = *(const float4*)(g_h + (long)s1 * F1 + t * 4);
            ax += w0 * v0.x + w1 * v1.x;
            ay += w0 * v0.y + w1 * v1.y;
            az += w0 * v0.z + w1 * v1.z;
            aw += w0 * v0.w + w1 * v1.w;
            den += w0 + w1;
        }
    }
    if (j < re) {
        int s0 = g_csr_src[j];
        if (active) {
            float  w = g_csr_w[j * 3 + head];
            float4 v = *(const float4*)(g_h + (long)s0 * F1 + t * 4);
            ax += w * v.x; ay += w * v.y; az += w * v.z; aw += w * v.w;
            den += w;
        }
    }
    if (active) {
        float inv = 1.0f / (den + 1e-16f);
        float4 r;
        r.x = elu1(ax * inv);
        r.y = elu1(ay * inv);
        r.z = elu1(az * inv);
        r.w = elu1(aw * inv);
        *(float4*)(g_out1 + (long)node * F1 + t * 4) = r;
    }
}

// ---------------- GEMM2 (fused fdot2) --------------------------------------
__global__ __launch_bounds__(256) void gemm2_kernel(
    const float* __restrict__ Wo,
    const float* __restrict__ a1o, const float* __restrict__ a2o, int n)
{
    __shared__ float As2[16][192];
    __shared__ float Ws[40][196];
    __shared__ float red2[16][2];
    int tid = threadIdx.x;
    int r0  = blockIdx.x * 16;

    for (int i = tid; i < F1 * NCLASS; i += 256) {
        int k = i / NCLASS, c = i % NCLASS;
        Ws[c][k] = Wo[i];
    }
    for (int j = tid; j < 16 * 48; j += 256) {
        int row = j / 48;
        int c4  = (j % 48) * 4;
        int gm  = r0 + row;
        float4 v = make_float4(0.f, 0.f, 0.f, 0.f);
        if (gm < n) v = *(const float4*)(g_out1 + (long)gm * F1 + c4);
        *(float4*)&As2[row][c4] = v;
    }
    if (tid < 32) red2[tid >> 1][tid & 1] = 0.f;
    __syncthreads();

#pragma unroll
    for (int it = 0; it < 3; it++) {
        int o = tid + it * 256;
        if (o < 16 * NCLASS) {
            int r = o / NCLASS, c = o % NCLASS;
            const float4* a4 = (const float4*)As2[r];
            const float4* w4 = (const float4*)Ws[c];
            float acc = 0.f;
#pragma unroll
            for (int k = 0; k < 48; k++) {
                float4 a = a4[k], w = w4[k];
                acc += a.x * w.x + a.y * w.y + a.z * w.z + a.w * w.w;
            }
            int gm = r0 + r;
            if (gm < n) g_h2[(long)gm * NCLASS + c] = acc;
            atomicAdd(&red2[r][0], acc * __ldg(a1o + c));
            atomicAdd(&red2[r][1], acc * __ldg(a2o + c));
        }
    }
    __syncthreads();
    if (tid < 16) {
        int gm = r0 + tid;
        if (gm < n) {
            g_f2d[gm] = red2[tid][0];
            g_f2s[gm] = red2[tid][1];
        }
    }
}

// ---------------- layer2 aggregation (fused weights, warp per node) --------
__global__ __launch_bounds__(64) void agg2_kernel(float* __restrict__ out, int n) {
    int node = blockIdx.x * 2 + (threadIdx.x >> 5);
    if (node >= n) return;
    int lane = threadIdx.x & 31;
    int rs = g_rowptr[node];
    int re = g_rowptr[node + 1];
    bool active = lane < 20;
    float fd = g_f2d[node];

    float a0 = 0.f, a1 = 0.f, den = 0.f;
    int j = rs;
    for (; j + 3 < re; j += 4) {
        int s[4];
#pragma unroll
        for (int u = 0; u < 4; u++) s[u] = g_csr_src[j + u];
        float w[4];
        float myw = 0.f;
        if (lane < 4) myw = att_w(fd + g_f2s[s[lane]]);
#pragma unroll
        for (int u = 0; u < 4; u++) w[u] = __shfl_sync(0xffffffffu, myw, u);
        if (active) {
#pragma unroll
            for (int u = 0; u < 4; u++) {
                float2 p = *(const float2*)(g_h2 + (long)s[u] * NCLASS + lane * 2);
                a0 += w[u] * p.x;
                a1 += w[u] * p.y;
                den += w[u];
            }
        }
    }
    for (; j < re; j++) {
        int s0 = g_csr_src[j];
        float w = 0.f;
        if (lane == 0) w = att_w(fd + g_f2s[s0]);
        w = __shfl_sync(0xffffffffu, w, 0);
        if (active) {
            float2 p = *(const float2*)(g_h2 + (long)s0 * NCLASS + lane * 2);
            a0 += w * p.x;
            a1 += w * p.y;
            den += w;
        }
    }
    if (active) {
        float inv = 1.0f / (den + 1e-16f);
        float2 r = make_float2(elu1(a0 * inv), elu1(a1 * inv));
        *(float2*)(out + (long)node * NCLASS + lane * 2) = r;
    }
}

// ---------------- launch ---------------------------------------------------
extern "C" void kernel_launch(void* const* d_in, const int* in_sizes, int n_in,
                              void* d_out, int out_size)
{
    const float* x   = (const float*)d_in[0];
    const void*  ei  = d_in[1];
    const float* W   = (const float*)d_in[2];
    const float* a1  = (const float*)d_in[3];
    const float* a2  = (const float*)d_in[4];
    const float* Wo  = (const float*)d_in[5];
    const float* a1o = (const float*)d_in[6];
    const float* a2o = (const float*)d_in[7];
    float* out = (float*)d_out;

    int n = in_sizes[0] / NFEAT;     // 100000
    int E = in_sizes[1] / 2;         // 3300000
    int nb = (n + 1023) / 1024;

    detect_kernel<<<1, 1>>>((const int*)ei);                 // 0
    zero_cnt_kernel<<<(n + 1023) / 1024, 1024>>>(n);         // 1
    count_kernel<<<(E + 255) / 256, 256>>>(ei, E);           // 2

    // gemm1 (+fused fdot1) at launch index 3 -> profiled
    gemm1_tc_kernel<<<(n + 127) / 128, 256>>>(x, W, a1, a2, n); // 3

    scanA_kernel<<<nb, 1024>>>(n);                           // 4
    scanB_kernel<<<1, 128>>>(nb);                            // 5
    scanC_kernel<<<nb, 1024>>>(n);                           // 6

    scatter_kernel<<<(E + 255) / 256, 256>>>(ei, E);         // 7
    agg1_kernel<<<n, 64>>>(n);                               // 8

    gemm2_kernel<<<(n + 15) / 16, 256>>>(Wo, a1o, a2o, n);   // 9
    agg2_kernel<<<(n + 1) / 2, 64>>>(out, n);                // 10
}

// round 17
// speedup vs baseline: 1.0164x; 1.0164x over previous
#include <cuda_runtime.h>
#include <cstdint>
#include <math.h>

#define NMAX   100000
#define EMAX   3400000
#define NFEAT  256
#define NHID   64
#define NHEADS 3
#define F1     192      // NHEADS*NHID
#define NCLASS 40

// ---------------- scratch (device globals; no allocations allowed) ----------
__device__ __align__(16) float g_h   [NMAX * F1];
__device__ __align__(16) float g_out1[NMAX * F1];
__device__ __align__(16) float g_h2  [NMAX * NCLASS];
__device__ float g_fd  [NMAX * NHEADS];
__device__ float g_fs  [NMAX * NHEADS];
__device__ float g_f2d [NMAX];
__device__ float g_f2s [NMAX];

__device__ int   g_is64;
__device__ int   g_cnt    [NMAX];
__device__ int   g_rowptr [NMAX + 1];
__device__ int   g_cursor [NMAX];
__device__ int   g_part   [128];
__device__ int   g_total;
__device__ int   g_csr_src[EMAX];
__device__ __align__(16) float g_csr_w [EMAX * 3];

__device__ __forceinline__ float elu1(float x) { return x > 0.f ? x : expm1f(x); }
__device__ __forceinline__ float att_w(float l) {
    float lr = l > 0.f ? l : 0.2f * l;
    return expf(-lr);
}

__device__ __forceinline__ int edge_at(const void* ei, long idx, int is64) {
    if (is64) return (int)((const long long*)ei)[idx];
    return ((const int*)ei)[idx];
}

__device__ __forceinline__ float tf32r(float x) {
    float r;
    asm("cvt.rna.tf32.f32 %0, %1;" : "=f"(r) : "f"(x));
    return r;
}

// ---------------- dtype detection -------------------------------------------
__global__ void detect_kernel(const int* __restrict__ ei32) {
    g_is64 = (ei32[1] == 0 && ei32[3] == 0 && ei32[5] == 0) ? 1 : 0;
}

// ---------------- CSR build --------------------------------------------------
__global__ void zero_cnt_kernel(int n) {
    int i = blockIdx.x * blockDim.x + threadIdx.x;
    if (i < n) g_cnt[i] = 0;
}

__global__ void count_kernel(const void* __restrict__ ei, int E) {
    int e = blockIdx.x * blockDim.x + threadIdx.x;
    if (e >= E) return;
    int is64 = g_is64;
    atomicAdd(&g_cnt[edge_at(ei, e, is64)], 1);
}

__global__ __launch_bounds__(1024) void scanA_kernel(int n) {
    __shared__ int sh[1024];
    int t = threadIdx.x;
    int i = blockIdx.x * 1024 + t;
    int v = (i < n) ? g_cnt[i] : 0;
    sh[t] = v;
    __syncthreads();
#pragma unroll
    for (int off = 1; off < 1024; off <<= 1) {
        int x = sh[t];
        int y = (t >= off) ? sh[t - off] : 0;
        __syncthreads();
        sh[t] = x + y;
        __syncthreads();
    }
    if (i < n) g_rowptr[i] = sh[t] - v;
    if (t == 1023) g_part[blockIdx.x] = sh[1023];
}

__global__ __launch_bounds__(128) void scanB_kernel(int nb) {
    __shared__ int sh[128];
    int t = threadIdx.x;
    int v = (t < nb) ? g_part[t] : 0;
    sh[t] = v;
    __syncthreads();
#pragma unroll
    for (int off = 1; off < 128; off <<= 1) {
        int x = sh[t];
        int y = (t >= off) ? sh[t - off] : 0;
        __syncthreads();
        sh[t] = x + y;
        __syncthreads();
    }
    g_part[t] = sh[t] - v;
    if (t == 127) g_total = sh[127];
}

__global__ __launch_bounds__(1024) void scanC_kernel(int n) {
    int i = blockIdx.x * 1024 + threadIdx.x;
    if (i < n) {
        int r = g_rowptr[i] + g_part[blockIdx.x];
        g_rowptr[i] = r;
        g_cursor[i] = r;
    }
    if (i == 0) g_rowptr[n] = g_total;
}

// scatter + layer1 edge weights
__global__ void scatter_kernel(const void* __restrict__ ei, int E) {
    int e = blockIdx.x * blockDim.x + threadIdx.x;
    if (e >= E) return;
    int is64 = g_is64;
    int dst = edge_at(ei, e, is64);
    int src = edge_at(ei, (long)E + e, is64);
    int pos = atomicAdd(&g_cursor[dst], 1);
    g_csr_src[pos] = src;
#pragma unroll
    for (int h = 0; h < 3; h++)
        g_csr_w[pos * 3 + h] = att_w(g_fd[dst * 3 + h] + g_fs[src * 3 + h]);
}

// ---------------- GEMM1 (tf32 TC, 3 heads, reg-staged, fused fdot1) --------
#define AS_S2 20    // A smem row stride (16 + 4 pad)
#define BS_S 200    // B smem row stride (192 + 8 pad)
#define NKT 16      // 256 / 16
__global__ __launch_bounds__(256, 1) void gemm1_tc_kernel(
    const float* __restrict__ x, const float* __restrict__ W,
    const float* __restrict__ a1, const float* __restrict__ a2, int n)
{
    __shared__ float As[2][128 * AS_S2];   // 2 x 10240 B
    __shared__ float Bs[2][16 * BS_S];     // 2 x 12800 B

    const int m0   = blockIdx.x * 128;
    const int tid  = threadIdx.x;

    const int wid   = tid >> 5;
    const int lane  = tid & 31;
    const int warpM = wid & 1;
    const int warpN = wid >> 1;
    const int g     = lane >> 2;
    const int tg    = lane & 3;

    const int arow0 = tid >> 2;
    const int ac40  = (tid & 3) * 4;
    const int arow1 = (tid + 256) >> 2;
    const int ac41  = ((tid + 256) & 3) * 4;
    int brow[3], bcc[3];
    const float* bsrc[3];
#pragma unroll
    for (int it = 0; it < 3; it++) {
        int j    = tid + it * 256;
        brow[it] = j / 48;
        int cc   = (j % 48) * 4;
        bcc[it]  = cc;
        int head = cc >> 6;
        int hc   = cc & 63;
        bsrc[it] = W + head * NFEAT * NHID + brow[it] * NHID + hc;
    }

    float c[4][6][4];
#pragma unroll
    for (int mt = 0; mt < 4; mt++)
#pragma unroll
        for (int nt = 0; nt < 6; nt++)
#pragma unroll
            for (int r = 0; r < 4; r++) c[mt][nt][r] = 0.f;

    float4 ra0, ra1, rb[3];
    {
        int gm0 = m0 + arow0, gm1 = m0 + arow1;
        ra0 = (gm0 < n) ? *(const float4*)(x + (long)gm0 * NFEAT + ac40)
                        : make_float4(0.f, 0.f, 0.f, 0.f);
        ra1 = (gm1 < n) ? *(const float4*)(x + (long)gm1 * NFEAT + ac41)
                        : make_float4(0.f, 0.f, 0.f, 0.f);
#pragma unroll
        for (int it = 0; it < 3; it++) rb[it] = *(const float4*)(bsrc[it]);
    }
    {
        float4 v;
        v = ra0; v.x = tf32r(v.x); v.y = tf32r(v.y); v.z = tf32r(v.z); v.w = tf32r(v.w);
        *(float4*)&As[0][arow0 * AS_S2 + ac40] = v;
        v = ra1; v.x = tf32r(v.x); v.y = tf32r(v.y); v.z = tf32r(v.z); v.w = tf32r(v.w);
        *(float4*)&As[0][arow1 * AS_S2 + ac41] = v;
#pragma unroll
        for (int it = 0; it < 3; it++) {
            v = rb[it]; v.x = tf32r(v.x); v.y = tf32r(v.y); v.z = tf32r(v.z); v.w = tf32r(v.w);
            *(float4*)&Bs[0][brow[it] * BS_S + bcc[it]] = v;
        }
    }
    __syncthreads();

    for (int t = 0; t < NKT; t++) {
        const int st = t & 1;
        if (t + 1 < NKT) {
            int kt = (t + 1) * 16;
            int gm0 = m0 + arow0, gm1 = m0 + arow1;
            ra0 = (gm0 < n) ? *(const float4*)(x + (long)gm0 * NFEAT + kt + ac40)
                            : make_float4(0.f, 0.f, 0.f, 0.f);
            ra1 = (gm1 < n) ? *(const float4*)(x + (long)gm1 * NFEAT + kt + ac41)
                            : make_float4(0.f, 0.f, 0.f, 0.f);
#pragma unroll
            for (int it = 0; it < 3; it++) rb[it] = *(const float4*)(bsrc[it] + kt * NHID);
        }

        const float* Asb = As[st];
        const float* Bsb = Bs[st];
#pragma unroll
        for (int ks = 0; ks < 2; ks++) {
            const int k0 = ks * 8;
            uint32_t a[4][4];
#pragma unroll
            for (int mt = 0; mt < 4; mt++) {
                int rbase = warpM * 64 + mt * 16;
                a[mt][0] = __float_as_uint(Asb[(rbase + g)     * AS_S2 + k0 + tg]);
                a[mt][1] = __float_as_uint(Asb[(rbase + g + 8) * AS_S2 + k0 + tg]);
                a[mt][2] = __float_as_uint(Asb[(rbase + g)     * AS_S2 + k0 + tg + 4]);
                a[mt][3] = __float_as_uint(Asb[(rbase + g + 8) * AS_S2 + k0 + tg + 4]);
            }
#pragma unroll
            for (int nt = 0; nt < 6; nt++) {
                int cbase = warpN * 48 + nt * 8;
                uint32_t b0 = __float_as_uint(Bsb[(k0 + tg)     * BS_S + cbase + g]);
                uint32_t b1 = __float_as_uint(Bsb[(k0 + tg + 4) * BS_S + cbase + g]);
#pragma unroll
                for (int mt = 0; mt < 4; mt++) {
                    asm volatile(
                        "mma.sync.aligned.m16n8k8.row.col.f32.tf32.tf32.f32 "
                        "{%0,%1,%2,%3}, {%4,%5,%6,%7}, {%8,%9}, {%0,%1,%2,%3};"
                        : "+f"(c[mt][nt][0]), "+f"(c[mt][nt][1]),
                          "+f"(c[mt][nt][2]), "+f"(c[mt][nt][3])
                        : "r"(a[mt][0]), "r"(a[mt][1]), "r"(a[mt][2]), "r"(a[mt][3]),
                          "r"(b0), "r"(b1));
                }
            }
        }

        if (t + 1 < NKT) {
            const int ns = (t + 1) & 1;
            float4 v;
            v = ra0; v.x = tf32r(v.x); v.y = tf32r(v.y); v.z = tf32r(v.z); v.w = tf32r(v.w);
            *(float4*)&As[ns][arow0 * AS_S2 + ac40] = v;
            v = ra1; v.x = tf32r(v.x); v.y = tf32r(v.y); v.z = tf32r(v.z); v.w = tf32r(v.w);
            *(float4*)&As[ns][arow1 * AS_S2 + ac41] = v;
#pragma unroll
            for (int it = 0; it < 3; it++) {
                v = rb[it]; v.x = tf32r(v.x); v.y = tf32r(v.y); v.z = tf32r(v.z); v.w = tf32r(v.w);
                *(float4*)&Bs[ns][brow[it] * BS_S + bcc[it]] = v;
            }
            __syncthreads();
        }
    }

    // epilogue: write g_h
#pragma unroll
    for (int mt = 0; mt < 4; mt++) {
        int row0 = m0 + warpM * 64 + mt * 16 + g;
#pragma unroll
        for (int nt = 0; nt < 6; nt++) {
            int col = warpN * 48 + nt * 8 + tg * 2;
            if (row0 < n)
                *(float2*)(g_h + (long)row0 * F1 + col) = make_float2(c[mt][nt][0], c[mt][nt][1]);
            if (row0 + 8 < n)
                *(float2*)(g_h + (long)(row0 + 8) * F1 + col) = make_float2(c[mt][nt][2], c[mt][nt][3]);
        }
    }

    // fused fdot1: per-row d = h.a1, s = h.a2 (reduce in smem, reuse As)
    __syncthreads();
    float* red = &As[0][0];                // 128 rows x 6 (d0,d1,d2,s0,s1,s2)
    for (int i = tid; i < 128 * 6; i += 256) red[i] = 0.f;
    __syncthreads();

    const int h0 = (warpN * 48) >> 6;
    const int h1 = (warpN * 48 + 47) >> 6;
#pragma unroll
    for (int mt = 0; mt < 4; mt++) {
#pragma unroll
        for (int half = 0; half < 2; half++) {
            int lrow = warpM * 64 + mt * 16 + g + half * 8;
            float dv[3] = {0.f, 0.f, 0.f};
            float sv[3] = {0.f, 0.f, 0.f};
#pragma unroll
            for (int nt = 0; nt < 6; nt++) {
                int col = warpN * 48 + nt * 8 + tg * 2;
                int h   = col >> 6;
                float c0 = c[mt][nt][half * 2 + 0];
                float c1 = c[mt][nt][half * 2 + 1];
                dv[h] += c0 * __ldg(a1 + col) + c1 * __ldg(a1 + col + 1);
                sv[h] += c0 * __ldg(a2 + col) + c1 * __ldg(a2 + col + 1);
            }
            for (int h = h0; h <= h1; h++) {
                atomicAdd(&red[lrow * 6 + h],     dv[h]);
                atomicAdd(&red[lrow * 6 + 3 + h], sv[h]);
            }
        }
    }
    __syncthreads();
    if (tid < 128) {
        int row = m0 + tid;
        if (row < n) {
#pragma unroll
            for (int h = 0; h < 3; h++) {
                g_fd[row * 3 + h] = red[tid * 6 + h];
                g_fs[row * 3 + h] = red[tid * 6 + 3 + h];
            }
        }
    }
}

// ---------------- layer1 aggregation (fp32 gather, 8-edge unroll) ----------
__global__ __launch_bounds__(64) void agg1_kernel(int n) {
    int node = blockIdx.x;
    if (node >= n) return;
    int t = threadIdx.x;
    int rs = g_rowptr[node];
    int re = g_rowptr[node + 1];
    bool active = t < 48;
    int head = t >> 4;

    float ax = 0.f, ay = 0.f, az = 0.f, aw = 0.f, den = 0.f;
    int j = rs;
    for (; j + 7 < re; j += 8) {
        int s[8];
#pragma unroll
        for (int u = 0; u < 8; u++) s[u] = g_csr_src[j + u];
        if (active) {
            float w[8];
#pragma unroll
            for (int u = 0; u < 8; u++) w[u] = g_csr_w[(j + u) * 3 + head];
            float4 v[8];
#pragma unroll
            for (int u = 0; u < 8; u++)
                v[u] = *(const float4*)(g_h + (long)s[u] * F1 + t * 4);
#pragma unroll
            for (int u = 0; u < 8; u++) {
                ax += w[u] * v[u].x;
                ay += w[u] * v[u].y;
                az += w[u] * v[u].z;
                aw += w[u] * v[u].w;
                den += w[u];
            }
        }
    }
    for (; j + 1 < re; j += 2) {
        int s0 = g_csr_src[j];
        int s1 = g_csr_src[j + 1];
        if (active) {
            float w0 = g_csr_w[(j + 0) * 3 + head];
            float w1 = g_csr_w[(j + 1) * 3 + head];
            float4 v0 = *(const float4*)(g_h + (long)s0 * F1 + t * 4);
            float4 v1 = *(const float4*)(g_h + (long)s1 * F1 + t * 4);
            ax += w0 * v0.x + w1 * v1.x;
            ay += w0 * v0.y + w1 * v1.y;
            az += w0 * v0.z + w1 * v1.z;
            aw += w0 * v0.w + w1 * v1.w;
            den += w0 + w1;
        }
    }
    if (j < re) {
        int s0 = g_csr_src[j];
        if (active) {
            float  w = g_csr_w[j * 3 + head];
            float4 v = *(const float4*)(g_h + (long)s0 * F1 + t * 4);
            ax += w * v.x; ay += w * v.y; az += w * v.z; aw += w * v.w;
            den += w;
        }
    }
    if (active) {
        float inv = 1.0f / (den + 1e-16f);
        float4 r;
        r.x = elu1(ax * inv);
        r.y = elu1(ay * inv);
        r.z = elu1(az * inv);
        r.w = elu1(aw * inv);
        *(float4*)(g_out1 + (long)node * F1 + t * 4) = r;
    }
}

// ---------------- GEMM2 (fused fdot2) --------------------------------------
__global__ __launch_bounds__(256) void gemm2_kernel(
    const float* __restrict__ Wo,
    const float* __restrict__ a1o, const float* __restrict__ a2o, int n)
{
    __shared__ float As2[16][192];
    __shared__ float Ws[40][196];
    __shared__ float red2[16][2];
    int tid = threadIdx.x;
    int r0  = blockIdx.x * 16;

    for (int i = tid; i < F1 * NCLASS; i += 256) {
        int k = i / NCLASS, c = i % NCLASS;
        Ws[c][k] = Wo[i];
    }
    for (int j = tid; j < 16 * 48; j += 256) {
        int row = j / 48;
        int c4  = (j % 48) * 4;
        int gm  = r0 + row;
        float4 v = make_float4(0.f, 0.f, 0.f, 0.f);
        if (gm < n) v = *(const float4*)(g_out1 + (long)gm * F1 + c4);
        *(float4*)&As2[row][c4] = v;
    }
    if (tid < 32) red2[tid >> 1][tid & 1] = 0.f;
    __syncthreads();

#pragma unroll
    for (int it = 0; it < 3; it++) {
        int o = tid + it * 256;
        if (o < 16 * NCLASS) {
            int r = o / NCLASS, c = o % NCLASS;
            const float4* a4 = (const float4*)As2[r];
            const float4* w4 = (const float4*)Ws[c];
            float acc = 0.f;
#pragma unroll
            for (int k = 0; k < 48; k++) {
                float4 a = a4[k], w = w4[k];
                acc += a.x * w.x + a.y * w.y + a.z * w.z + a.w * w.w;
            }
            int gm = r0 + r;
            if (gm < n) g_h2[(long)gm * NCLASS + c] = acc;
            atomicAdd(&red2[r][0], acc * __ldg(a1o + c));
            atomicAdd(&red2[r][1], acc * __ldg(a2o + c));
        }
    }
    __syncthreads();
    if (tid < 16) {
        int gm = r0 + tid;
        if (gm < n) {
            g_f2d[gm] = red2[tid][0];
            g_f2s[gm] = red2[tid][1];
        }
    }
}

// ---------------- layer2 aggregation (fused weights, warp per node) --------
__global__ __launch_bounds__(64) void agg2_kernel(float* __restrict__ out, int n) {
    int node = blockIdx.x * 2 + (threadIdx.x >> 5);
    if (node >= n) return;
    int lane = threadIdx.x & 31;
    int rs = g_rowptr[node];
    int re = g_rowptr[node + 1];
    bool active = lane < 20;
    float fd = g_f2d[node];

    float a0 = 0.f, a1 = 0.f, den = 0.f;
    int j = rs;
    for (; j + 3 < re; j += 4) {
        int s[4];
#pragma unroll
        for (int u = 0; u < 4; u++) s[u] = g_csr_src[j + u];
        float w[4];
        float myw = 0.f;
        if (lane < 4) myw = att_w(fd + g_f2s[s[lane]]);
#pragma unroll
        for (int u = 0; u < 4; u++) w[u] = __shfl_sync(0xffffffffu, myw, u);
        if (active) {
#pragma unroll
            for (int u = 0; u < 4; u++) {
                float2 p = *(const float2*)(g_h2 + (long)s[u] * NCLASS + lane * 2);
                a0 += w[u] * p.x;
                a1 += w[u] * p.y;
                den += w[u];
            }
        }
    }
    for (; j < re; j++) {
        int s0 = g_csr_src[j];
        float w = 0.f;
        if (lane == 0) w = att_w(fd + g_f2s[s0]);
        w = __shfl_sync(0xffffffffu, w, 0);
        if (active) {
            float2 p = *(const float2*)(g_h2 + (long)s0 * NCLASS + lane * 2);
            a0 += w * p.x;
            a1 += w * p.y;
            den += w;
        }
    }
    if (active) {
        float inv = 1.0f / (den + 1e-16f);
        float2 r = make_float2(elu1(a0 * inv), elu1(a1 * inv));
        *(float2*)(out + (long)node * NCLASS + lane * 2) = r;
    }
}

// ---------------- launch ---------------------------------------------------
extern "C" void kernel_launch(void* const* d_in, const int* in_sizes, int n_in,
                              void* d_out, int out_size)
{
    const float* x   = (const float*)d_in[0];
    const void*  ei  = d_in[1];
    const float* W   = (const float*)d_in[2];
    const float* a1  = (const float*)d_in[3];
    const float* a2  = (const float*)d_in[4];
    const float* Wo  = (const float*)d_in[5];
    const float* a1o = (const float*)d_in[6];
    const float* a2o = (const float*)d_in[7];
    float* out = (float*)d_out;

    int n = in_sizes[0] / NFEAT;     // 100000
    int E = in_sizes[1] / 2;         // 3300000
    int nb = (n + 1023) / 1024;

    detect_kernel<<<1, 1>>>((const int*)ei);                 // 0
    zero_cnt_kernel<<<(n + 1023) / 1024, 1024>>>(n);         // 1
    count_kernel<<<(E + 255) / 256, 256>>>(ei, E);           // 2

    // gemm1 (+fused fdot1) at launch index 3 -> profiled
    gemm1_tc_kernel<<<(n + 127) / 128, 256>>>(x, W, a1, a2, n); // 3

    scanA_kernel<<<nb, 1024>>>(n);                           // 4
    scanB_kernel<<<1, 128>>>(nb);                            // 5
    scanC_kernel<<<nb, 1024>>>(n);                           // 6

    scatter_kernel<<<(E + 255) / 256, 256>>>(ei, E);         // 7
    agg1_kernel<<<n, 64>>>(n);                               // 8

    gemm2_kernel<<<(n + 15) / 16, 256>>>(Wo, a1o, a2o, n);   // 9
    agg2_kernel<<<(n + 1) / 2, 64>>>(out, n);                // 10
}